// round 15
// baseline (speedup 1.0000x reference)
#include <cuda_runtime.h>
#include <cuda_bf16.h>
#include <cstdint>

// Problem constants
#define B  4
#define C  64
#define H  128
#define W  128
#define O  64
#define KH 3
#define KW 3
#define K  9
#define CK (C*K)      // 576
#define HW (H*W)      // 16384
#define NPIX (B*HW)   // 65536

#define GPX 128           // pixels per tile (one image row)
#define NTILES (NPIX/GPX) // 512
#define NCH 9             // kc chunks of 64 (== tap k)
#define NT 256            // threads

// Padded smem row stride: 64 bf16 + 8 pad = 72 bf16 = 144 bytes
#define SSTR 144

// ---- fused-kernel smem layout (bytes) ----
#define SA_H   0                         // A hi  [128][SSTR]
#define SA_L   (GPX * SSTR)              // 18432: A lo
#define SW0    (2 * GPX * SSTR)          // 36864: W double buffer
#define WBUF   (2 * O * SSTR)            // 18432 per buffer (hi at +0, lo at +9216)
#define SPAR   (SW0 + 2 * WBUF)          // 73728: params
#define NPAR   (K * GPX)                 // 1152 tasks
#define SME_TOT (SPAR + 6 * NPAR * 4)    // 101376 (~99KB)

// Scratch (__device__ globals per allocation rules)
__device__ float          g_xt[B * HW * C];   // NHWC input fp32, 16.8MB
__device__ __nv_bfloat16  g_wh[K * O * C];    // weight hi, [k][o][c]
__device__ __nv_bfloat16  g_wl[K * O * C];    // weight lo

// ---------------- PTX helpers ----------------
__device__ __forceinline__ uint32_t smem_u32(const void* p) {
    uint32_t a;
    asm("{ .reg .u64 t; cvta.to.shared.u64 t, %1; cvt.u32.u64 %0, t; }" : "=r"(a) : "l"(p));
    return a;
}
__device__ __forceinline__ void ldsm_x4(uint32_t* r, uint32_t addr) {
    asm volatile("ldmatrix.sync.aligned.m8n8.x4.shared.b16 {%0,%1,%2,%3}, [%4];"
        : "=r"(r[0]), "=r"(r[1]), "=r"(r[2]), "=r"(r[3]) : "r"(addr));
}
__device__ __forceinline__ void ldsm_x2(uint32_t* r, uint32_t addr) {
    asm volatile("ldmatrix.sync.aligned.m8n8.x2.shared.b16 {%0,%1}, [%2];"
        : "=r"(r[0]), "=r"(r[1]) : "r"(addr));
}
__device__ __forceinline__ void mma16816(float* d, const uint32_t* a, const uint32_t* b) {
    asm volatile("mma.sync.aligned.m16n8k16.row.col.f32.bf16.bf16.f32 "
        "{%0,%1,%2,%3}, {%4,%5,%6,%7}, {%8,%9}, {%0,%1,%2,%3};"
        : "+f"(d[0]), "+f"(d[1]), "+f"(d[2]), "+f"(d[3])
        : "r"(a[0]), "r"(a[1]), "r"(a[2]), "r"(a[3]), "r"(b[0]), "r"(b[1]));
}
__device__ __forceinline__ void cp16(uint32_t saddr, const void* gptr) {
    asm volatile("cp.async.cg.shared.global [%0], [%1], 16;" :: "r"(saddr), "l"(gptr));
}

// ---------------------------------------------------------------------------
// Kernel A: NCHW -> NHWC transpose (fp32, sampler input)
// ---------------------------------------------------------------------------
__global__ void transpose_kernel(const float* __restrict__ x) {
    __shared__ float tile[32][33];
    int b  = blockIdx.z;
    int c0 = blockIdx.y * 32;
    int s0 = blockIdx.x * 32;
    int tx = threadIdx.x, ty = threadIdx.y;   // block (32, 8)
    #pragma unroll
    for (int i = 0; i < 32; i += 8)
        tile[ty + i][tx] = x[(b * C + c0 + ty + i) * HW + s0 + tx];
    __syncthreads();
    #pragma unroll
    for (int i = 0; i < 32; i += 8)
        g_xt[(b * HW + s0 + ty + i) * C + c0 + tx] = tile[tx][ty + i];
}

// ---------------------------------------------------------------------------
// Kernel B: weight split+repack  W[o][c][k] -> Wh/Wl [k][o][c] bf16
// ---------------------------------------------------------------------------
__global__ void wsplit_kernel(const float* __restrict__ w) {
    int idx = blockIdx.x * 256 + threadIdx.x;
    if (idx < K * O * C) {
        int k = idx >> 12;
        int o = (idx >> 6) & 63;
        int c = idx & 63;
        float v = w[(o * C + c) * K + k];
        __nv_bfloat16 hi = __float2bfloat16(v);
        __nv_bfloat16 lo = __float2bfloat16(v - __bfloat162float(hi));
        g_wh[idx] = hi;
        g_wl[idx] = lo;
    }
}

// ---------------------------------------------------------------------------
// Fused kernel: per CTA = one image row (128 px) x 64 o.
//   Phase 0: params for all 9 taps (coalesced)
//   Per tap-chunk: sample 128px x 64c -> smem A (hi/lo), then HMMA.
//   Weights cp.async double-buffered. val never leaves the SM.
// ---------------------------------------------------------------------------
__global__ __launch_bounds__(NT, 2)
void fused_kernel(const float* __restrict__ offset,
                  const float* __restrict__ mask,
                  const float* __restrict__ bias,
                  float* __restrict__ out) {
    extern __shared__ char smem[];
    const uint32_t sb = smem_u32(smem);
    int*   s_y0  = (int*)  (smem + SPAR);
    int*   s_x0  = s_y0  + NPAR;
    float* s_w00 = (float*)(s_x0 + NPAR);
    float* s_w01 = s_w00 + NPAR;
    float* s_w10 = s_w01 + NPAR;
    float* s_w11 = s_w10 + NPAR;

    const int tid  = threadIdx.x;
    const int wid  = tid >> 5;
    const int lane = tid & 31;
    const int tile = blockIdx.x;
    const int b    = tile >> 7;            // tile*128/HW
    const int row  = tile & 127;           // ho; wo = px (full row)

    // ---- Phase 0: params for all taps (coalesced over px)
    for (int t = tid; t < NPAR; t += NT) {
        int k  = t >> 7;
        int px = t & 127;
        float offy = offset[((b * 2 * K + 2 * k    ) * H + row) * W + px];
        float offx = offset[((b * 2 * K + 2 * k + 1) * H + row) * W + px];
        float m    = mask  [((b * K + k) * H + row) * W + px];
        float py = offy + (float)(k / KW) + (float)(row - 1);   // sh=dh=1, ph=1
        float px_f = offx + (float)(k % KW) + (float)(px - 1);
        float y0f = floorf(py), x0f = floorf(px_f);
        float ly = py - y0f, lx = px_f - x0f;
        s_y0[t] = (int)y0f;
        s_x0[t] = (int)x0f;
        s_w00[t] = (1.f - ly) * (1.f - lx) * m;
        s_w01[t] = (1.f - ly) * lx * m;
        s_w10[t] = ly * (1.f - lx) * m;
        s_w11[t] = ly * lx * m;
    }

    // ---- weight staging setup (cp.async double buffer)
    const uint4* wh4 = (const uint4*)g_wh;
    const uint4* wl4 = (const uint4*)g_wl;
    uint32_t sBoff[2];
    #pragma unroll
    for (int j = 0; j < 2; j++) {
        int e = j * NT + tid;              // 0..511
        sBoff[j] = (e >> 3) * SSTR + (e & 7) * 16;
    }
    auto issueW = [&](int ch) {
        uint32_t base = sb + SW0 + (ch & 1) * WBUF;
        size_t bbase = (size_t)ch * 512;
        #pragma unroll
        for (int j = 0; j < 2; j++) {
            int e = j * NT + tid;
            cp16(base + sBoff[j], wh4 + bbase + e);
            cp16(base + 9216 + sBoff[j], wl4 + bbase + e);
        }
        asm volatile("cp.async.commit_group;" ::: "memory");
    };
    issueW(0);

    // ---- MMA constants
    const int px0 = (wid & 3) * 32;        // warp px base
    const int o0  = (wid >> 2) * 32;       // warp o base
    const uint32_t aOffH = sb + SA_H + (px0 + (lane & 15)) * SSTR + (lane >> 4) * 16;
    const uint32_t aOffL = aOffH + (SA_L - SA_H);
    const uint32_t bRel  = (o0 + (lane & 7)) * SSTR + ((lane >> 3) & 1) * 16;

    float acc[2][4][4];
    #pragma unroll
    for (int i = 0; i < 2; i++)
        #pragma unroll
        for (int j = 0; j < 4; j++)
            #pragma unroll
            for (int r = 0; r < 4; r++) acc[i][j][r] = 0.f;

    const float* xb = g_xt + b * HW * C;
    const int coff = lane * 2;
    const int spx0 = wid * 16;             // sampling px base for this warp

    __syncthreads();                       // params ready

    #pragma unroll 1
    for (int ch = 0; ch < NCH; ch++) {
        // prefetch next weight chunk while sampling
        if (ch + 1 < NCH) issueW(ch + 1);

        // ---- sample tap ch: this warp covers px spx0..spx0+15, lane = c-pair
        #pragma unroll 4
        for (int j = 0; j < 16; j++) {
            int px = spx0 + j;
            int t  = ch * 128 + px;
            int y0 = s_y0[t];
            int x0 = s_x0[t];
            float w00 = s_w00[t], w01 = s_w01[t], w10 = s_w10[t], w11 = s_w11[t];

            bool yv0 = (unsigned)y0 < H;
            bool yv1 = (unsigned)(y0 + 1) < H;
            bool xv0 = (unsigned)x0 < W;
            bool xv1 = (unsigned)(x0 + 1) < W;

            float2 v00 = {0.f, 0.f}, v01 = {0.f, 0.f}, v10 = {0.f, 0.f}, v11 = {0.f, 0.f};
            if (yv0 && xv0) v00 = *(const float2*)(xb + ((y0    ) * W + x0    ) * C + coff);
            if (yv0 && xv1) v01 = *(const float2*)(xb + ((y0    ) * W + x0 + 1) * C + coff);
            if (yv1 && xv0) v10 = *(const float2*)(xb + ((y0 + 1) * W + x0    ) * C + coff);
            if (yv1 && xv1) v11 = *(const float2*)(xb + ((y0 + 1) * W + x0 + 1) * C + coff);

            float rx = w00 * v00.x + w01 * v01.x + w10 * v10.x + w11 * v11.x;
            float ry = w00 * v00.y + w01 * v01.y + w10 * v10.y + w11 * v11.y;

            __nv_bfloat16 hx = __float2bfloat16(rx);
            __nv_bfloat16 hy = __float2bfloat16(ry);
            __nv_bfloat16 lx2 = __float2bfloat16(rx - __bfloat162float(hx));
            __nv_bfloat16 ly2 = __float2bfloat16(ry - __bfloat162float(hy));

            uint32_t aoff = px * SSTR + lane * 4;
            *(__nv_bfloat162*)(smem + SA_H + aoff) = __nv_bfloat162(hx, hy);
            *(__nv_bfloat162*)(smem + SA_L + aoff) = __nv_bfloat162(lx2, ly2);
        }

        // weights for this chunk must be resident
        if (ch + 1 < NCH)
            asm volatile("cp.async.wait_group 1;" ::: "memory");
        else
            asm volatile("cp.async.wait_group 0;" ::: "memory");
        __syncthreads();                   // A tile + W buffer ready

        const uint32_t wb = sb + SW0 + (ch & 1) * WBUF;
        const uint32_t bH = wb + bRel;
        const uint32_t bL = bH + 9216;

        #pragma unroll
        for (int s = 0; s < 4; s++) {      // 4 K-steps of 16
            uint32_t ah[2][4], al[2][4], bh[4][2], bl[4][2];
            #pragma unroll
            for (int mt = 0; mt < 2; mt++) {
                ldsm_x4(ah[mt], aOffH + mt * 16 * SSTR + s * 32);
                ldsm_x4(al[mt], aOffL + mt * 16 * SSTR + s * 32);
            }
            #pragma unroll
            for (int nt = 0; nt < 4; nt++) {
                ldsm_x2(bh[nt], bH + nt * 8 * SSTR + s * 32);
                ldsm_x2(bl[nt], bL + nt * 8 * SSTR + s * 32);
            }
            #pragma unroll
            for (int mt = 0; mt < 2; mt++)
                #pragma unroll
                for (int nt = 0; nt < 4; nt++) {
                    mma16816(acc[mt][nt], ah[mt], bh[nt]);
                    mma16816(acc[mt][nt], al[mt], bh[nt]);
                    mma16816(acc[mt][nt], ah[mt], bl[nt]);
                }
        }
        __syncthreads();                   // MMA reads done before next sample
    }

    // ---- epilogue: D[px][o]; lane l -> px = l/4 (+8), o = (l%4)*2 (+1)
    const int hw0 = tile << 7;
    float* ob = out + (size_t)b * O * HW + (hw0 & (HW - 1));
    #pragma unroll
    for (int nt = 0; nt < 4; nt++) {
        int o_b = o0 + nt * 8 + (lane & 3) * 2;
        float bv0 = __ldg(&bias[o_b]);
        float bv1 = __ldg(&bias[o_b + 1]);
        #pragma unroll
        for (int mt = 0; mt < 2; mt++) {
            int px = px0 + mt * 16 + (lane >> 2);
            float* p0 = ob + (size_t)o_b * HW + px;
            p0[0]      = acc[mt][nt][0] + bv0;
            p0[HW]     = acc[mt][nt][1] + bv1;
            p0[8]      = acc[mt][nt][2] + bv0;
            p0[HW + 8] = acc[mt][nt][3] + bv1;
        }
    }
}

// ---------------------------------------------------------------------------
extern "C" void kernel_launch(void* const* d_in, const int* in_sizes, int n_in,
                              void* d_out, int out_size) {
    const float* x      = (const float*)d_in[0];
    const float* offset = (const float*)d_in[1];
    const float* mask   = (const float*)d_in[2];
    const float* weight = (const float*)d_in[3];
    const float* bias   = (const float*)d_in[4];
    float* out = (float*)d_out;

    {   // A: transpose to NHWC
        dim3 grid(HW / 32, C / 32, B);
        dim3 block(32, 8);
        transpose_kernel<<<grid, block>>>(x);
    }
    {   // B: weight split/repack
        wsplit_kernel<<<(K * O * C + 255) / 256, 256>>>(weight);
    }
    {   // C: fused sample + HMMA GEMM
        cudaFuncSetAttribute(fused_kernel,
                             cudaFuncAttributeMaxDynamicSharedMemorySize, SME_TOT);
        fused_kernel<<<NTILES, NT, SME_TOT>>>(offset, mask, bias, out);
    }
}